// round 11
// baseline (speedup 1.0000x reference)
#include <cuda_runtime.h>

#define BB     32
#define NVV    6890
#define NFF    13776
#define MAXC   8
#define NCC    (NFF * MAXC)          // 110208
#define NPAIRS (BB * NCC)            // 3,526,656 = 13776 * 256 exactly
#define NREC   (BB * NFF)            // 440,832 records
#define SIGMA_F  0.5f
#define SIGMA2_F 0.25f
#define TPB    256
#define GRID_PAIR (NPAIRS / TPB)     // 13776, exact

// 64B record per (b, face): {v0.xyz, cx}, {v1.xyz, cy}, {v2.xyz, cz}, {nx,ny,nz, 0}
// 64B-aligned -> exactly 2 L2 sectors per record. ~28.2 MB (fits L2).
__device__ __align__(64) float4 g_recs[(size_t)NREC * 4];
__device__ double g_acc;
__device__ unsigned int g_cnt;

// ---------------------------------------------------------------------------
// Build: per (b, face) gather 3 verts, precompute centroid + normalized normal.
// ---------------------------------------------------------------------------
__global__ __launch_bounds__(256) void build_recs_kernel(
    const float* __restrict__ verts, const int* __restrict__ faces)
{
    int t = blockIdx.x * blockDim.x + threadIdx.x;
    if (t == 0) { g_acc = 0.0; g_cnt = 0u; }
    if (t >= NREC) return;
    int b = t / NFF;
    int f = t - b * NFF;
    int i0 = faces[3 * f + 0];
    int i1 = faces[3 * f + 1];
    int i2 = faces[3 * f + 2];
    const float* vb = verts + (size_t)b * NVV * 3;
    float v0x = vb[3*i0], v0y = vb[3*i0+1], v0z = vb[3*i0+2];
    float v1x = vb[3*i1], v1y = vb[3*i1+1], v1z = vb[3*i1+2];
    float v2x = vb[3*i2], v2y = vb[3*i2+1], v2z = vb[3*i2+2];

    const float third = 1.0f / 3.0f;
    float cx = (v0x + v1x + v2x) * third;
    float cy = (v0y + v1y + v2y) * third;
    float cz = (v0z + v1z + v2z) * third;

    float e1x = v1x - v0x, e1y = v1y - v0y, e1z = v1z - v0z;
    float e2x = v2x - v0x, e2y = v2y - v0y, e2z = v2z - v0z;
    float nx = e1y * e2z - e1z * e2y;
    float ny = e1z * e2x - e1x * e2z;
    float nz = e1x * e2y - e1y * e2x;
    float nn = sqrtf(fmaf(nx, nx, fmaf(ny, ny, nz * nz)));
    float inv = 1.0f / (nn + 1e-8f);
    nx *= inv; ny *= inv; nz *= inv;

    float4* dst = &g_recs[(size_t)t * 4];
    dst[0] = make_float4(v0x, v0y, v0z, cx);
    dst[1] = make_float4(v1x, v1y, v1z, cy);
    dst[2] = make_float4(v2x, v2y, v2z, cz);
    dst[3] = make_float4(nx,  ny,  nz,  0.0f);
}

// ---------------------------------------------------------------------------
// Penetration of query verts (Q record) inside cone field of A record.
// c = (a0.w, a1.w, a2.w); n = an.xyz (pre-normalized). Same math as reference.
// ---------------------------------------------------------------------------
__device__ __forceinline__ float pen_dir(
    float4 a0, float4 a1, float4 a2, float4 an,
    float4 q0, float4 q1, float4 q2)
{
    float cx = a0.w, cy = a1.w, cz = a2.w;

    float d0x = q0.x - cx, d0y = q0.y - cy, d0z = q0.z - cz;
    float d1x = q1.x - cx, d1y = q1.y - cy, d1z = q1.z - cz;
    float d2x = q2.x - cx, d2y = q2.y - cy, d2z = q2.z - cz;

    float r20 = fmaf(d0x, d0x, fmaf(d0y, d0y, d0z * d0z));
    float r21 = fmaf(d1x, d1x, fmaf(d1y, d1y, d1z * d1z));
    float r22 = fmaf(d2x, d2x, fmaf(d2y, d2y, d2z * d2z));

    if (fminf(fminf(r20, r21), r22) >= SIGMA2_F) return 0.0f;

    float nx = an.x, ny = an.y, nz = an.z;
    float s = 0.0f;
    if (r20 < SIGMA2_F) {
        float h = fmaf(d0x, nx, fmaf(d0y, ny, d0z * nz));
        if (h < 0.0f) { float phi = SIGMA_F - sqrtf(r20); s = fmaf(phi * h, h, s); }
    }
    if (r21 < SIGMA2_F) {
        float h = fmaf(d1x, nx, fmaf(d1y, ny, d1z * nz));
        if (h < 0.0f) { float phi = SIGMA_F - sqrtf(r21); s = fmaf(phi * h, h, s); }
    }
    if (r22 < SIGMA2_F) {
        float h = fmaf(d2x, nx, fmaf(d2y, ny, d2z * nz));
        if (h < 0.0f) { float phi = SIGMA_F - sqrtf(r22); s = fmaf(phi * h, h, s); }
    }
    return s;
}

// ---------------------------------------------------------------------------
// Pair kernel: 256 pairs/block. Cooperative 64B-record gather via lane quads
// (each LDG.128 covers 8 records -> ~8 L1 wavefronts instead of 32), staged in
// shared memory. RSTRIDE=20 floats (80B): every record row is 16B-aligned so
// STS.128/LDS.128 are legal; worst case 2-way bank conflict (negligible).
// Last block finalizes the output.
// ---------------------------------------------------------------------------
#define RSTRIDE 20   // floats per record row in smem (64B data + 16B pad)

__global__ __launch_bounds__(TPB) void pair_kernel(
    const int2* __restrict__ cidx,
    const float* __restrict__ weight,
    float* __restrict__ out)
{
    __shared__ float s_rec[2 * TPB * RSTRIDE];   // 512 records * 80B = 40 KB
    __shared__ int   s_ridx[2 * TPB];
    __shared__ float s_wsum[TPB / 32];

    int tid = threadIdx.x;
    int p   = blockIdx.x * TPB + tid;            // grid is exact, no bounds check

    // Phase 1: record indices for this block's 512 gathers
    int2 ids  = cidx[p];
    int  b    = p / NCC;
    bool valid = ids.x >= 0;
    int  recbase = b * NFF;
    s_ridx[2 * tid]     = recbase + (valid ? ids.x : 0);
    s_ridx[2 * tid + 1] = recbase + max(ids.y, 0);
    __syncthreads();

    // Phase 2: cooperative load. Lane quad (tid&3) loads one float4 of each record.
    int c = tid & 3;
    #pragma unroll
    for (int r = tid >> 2; r < 2 * TPB; r += TPB / 4) {
        int g = s_ridx[r];
        float4 v = __ldg(&g_recs[(size_t)g * 4 + c]);
        *(float4*)&s_rec[r * RSTRIDE + c * 4] = v;
    }
    __syncthreads();

    // Phase 3: compute
    const float* R = &s_rec[(2 * tid)     * RSTRIDE];
    const float* I = &s_rec[(2 * tid + 1) * RSTRIDE];
    float4 r0 = *(const float4*)(R +  0);
    float4 r1 = *(const float4*)(R +  4);
    float4 r2 = *(const float4*)(R +  8);
    float4 rn = *(const float4*)(R + 12);
    float4 i0 = *(const float4*)(I +  0);
    float4 i1 = *(const float4*)(I +  4);
    float4 i2 = *(const float4*)(I +  8);
    float4 in = *(const float4*)(I + 12);

    float pen = 0.0f;
    if (valid) {
        pen = pen_dir(r0, r1, r2, rn, i0, i1, i2)
            + pen_dir(i0, i1, i2, in, r0, r1, r2);
    }

    // Block reduction (all terms >= 0)
    #pragma unroll
    for (int o = 16; o > 0; o >>= 1)
        pen += __shfl_down_sync(0xffffffffu, pen, o);
    int lane = tid & 31, w = tid >> 5;
    if (lane == 0) s_wsum[w] = pen;
    __syncthreads();
    if (w == 0) {
        float v = (lane < TPB / 32) ? s_wsum[lane] : 0.0f;
        #pragma unroll
        for (int o = 4; o > 0; o >>= 1)
            v += __shfl_down_sync(0xffu, v, o);
        if (lane == 0) {
            atomicAdd(&g_acc, (double)v);
            __threadfence();
            unsigned int done = atomicAdd(&g_cnt, 1u);
            if (done == (unsigned int)(GRID_PAIR - 1)) {
                // atomicAdd read-back guarantees we see all prior L2 atomics
                double total = atomicAdd(&g_acc, 0.0);
                out[0] = (float)(total * (1.0 / (double)BB)) * weight[0];
            }
        }
    }
}

extern "C" void kernel_launch(void* const* d_in, const int* in_sizes, int n_in,
                              void* d_out, int out_size)
{
    // metadata order: pose, joints, points, keypoints, vertices, weight, faces, collision_idxs
    const float* vertices = (const float*)d_in[4];
    const float* weight   = (const float*)d_in[5];
    const int*   faces    = (const int*)d_in[6];
    const int2*  cidx     = (const int2*)d_in[7];

    build_recs_kernel<<<(NREC + 255) / 256, 256>>>(vertices, faces);
    pair_kernel<<<GRID_PAIR, TPB>>>(cidx, weight, (float*)d_out);
}

// round 13
// speedup vs baseline: 1.5922x; 1.5922x over previous
#include <cuda_runtime.h>

#define BB     32
#define NVV    6890
#define NFF    13776
#define MAXC   8
#define NCC    (NFF * MAXC)          // 110208
#define NPAIRS (BB * NCC)            // 3,526,656 = 13776 * 256 exactly
#define NREC   (BB * NFF)            // 440,832 records
#define SIGMA_F  0.5f
#define SIGMA2_F 0.25f
#define TPB    256
#define PAIRS_PER_BLOCK 256          // 8 warps * 8 quads * 4 iters
#define GRID_PAIR (NPAIRS / PAIRS_PER_BLOCK)   // 13776, exact

// 64B record per (b, face): {v0.xyz, cx}, {v1.xyz, cy}, {v2.xyz, cz}, {nx,ny,nz, 0}
// 64B-aligned -> exactly 2 L2 sectors per record. ~28.2 MB.
__device__ __align__(64) float4 g_recs[(size_t)NREC * 4];
__device__ double g_acc;
__device__ unsigned int g_cnt;

// ---------------------------------------------------------------------------
// Build: per (b, face) gather 3 verts, precompute centroid + normalized normal.
// ---------------------------------------------------------------------------
__global__ __launch_bounds__(256) void build_recs_kernel(
    const float* __restrict__ verts, const int* __restrict__ faces)
{
    int t = blockIdx.x * blockDim.x + threadIdx.x;
    if (t == 0) { g_acc = 0.0; g_cnt = 0u; }
    if (t >= NREC) return;
    int b = t / NFF;
    int f = t - b * NFF;
    int i0 = faces[3 * f + 0];
    int i1 = faces[3 * f + 1];
    int i2 = faces[3 * f + 2];
    const float* vb = verts + (size_t)b * NVV * 3;
    float v0x = vb[3*i0], v0y = vb[3*i0+1], v0z = vb[3*i0+2];
    float v1x = vb[3*i1], v1y = vb[3*i1+1], v1z = vb[3*i1+2];
    float v2x = vb[3*i2], v2y = vb[3*i2+1], v2z = vb[3*i2+2];

    const float third = 1.0f / 3.0f;
    float cx = (v0x + v1x + v2x) * third;
    float cy = (v0y + v1y + v2y) * third;
    float cz = (v0z + v1z + v2z) * third;

    float e1x = v1x - v0x, e1y = v1y - v0y, e1z = v1z - v0z;
    float e2x = v2x - v0x, e2y = v2y - v0y, e2z = v2z - v0z;
    float nx = e1y * e2z - e1z * e2y;
    float ny = e1z * e2x - e1x * e2z;
    float nz = e1x * e2y - e1y * e2x;
    float nn = sqrtf(fmaf(nx, nx, fmaf(ny, ny, nz * nz)));
    float inv = 1.0f / (nn + 1e-8f);
    nx *= inv; ny *= inv; nz *= inv;

    float4* dst = &g_recs[(size_t)t * 4];
    dst[0] = make_float4(v0x, v0y, v0z, cx);
    dst[1] = make_float4(v1x, v1y, v1z, cy);
    dst[2] = make_float4(v2x, v2y, v2z, cz);
    dst[3] = make_float4(nx,  ny,  nz,  0.0f);
}

// ---------------------------------------------------------------------------
// Pair kernel, quad-per-pair: lanes 4q..4q+3 own one pair. Lane c loads float4
// c of each record (4 lanes x 16B = one 64B record = ONE L1 wavefront), quads
// exchange centroid/normal via width-4 shuffles (ALU pipe, not L1tex), lanes
// 0-2 evaluate one query vertex per direction. No bulk smem. 2 wavefronts/pair.
// ---------------------------------------------------------------------------
__global__ __launch_bounds__(TPB) void pair_kernel(
    const int2* __restrict__ cidx,
    const float* __restrict__ weight,
    float* __restrict__ out)
{
    __shared__ float s_wsum[TPB / 32];

    const unsigned FULL = 0xffffffffu;
    int tid  = threadIdx.x;
    int lane = tid & 31;
    int w    = tid >> 5;
    int quad = lane >> 2;
    int lc   = lane & 3;

    float pen = 0.0f;

    #pragma unroll
    for (int it = 0; it < 4; ++it) {
        int p = blockIdx.x * PAIRS_PER_BLOCK + it * 64 + w * 8 + quad;
        int2 ids = cidx[p];                       // 4 lanes/quad same addr -> bcast
        bool valid = ids.x >= 0;
        int  b  = p / NCC;
        int  rb = b * NFF;
        int  ra = rb + (valid ? ids.x : 0);
        int  ri = rb + max(ids.y, 0);

        float4 fA = __ldg(&g_recs[(size_t)ra * 4 + lc]);
        float4 fI = __ldg(&g_recs[(size_t)ri * 4 + lc]);

        // quad broadcasts: centroids live in .w of lanes 0..2, normals in lane 3
        float cAx = __shfl_sync(FULL, fA.w, 0, 4);
        float cAy = __shfl_sync(FULL, fA.w, 1, 4);
        float cAz = __shfl_sync(FULL, fA.w, 2, 4);
        float nAx = __shfl_sync(FULL, fA.x, 3, 4);
        float nAy = __shfl_sync(FULL, fA.y, 3, 4);
        float nAz = __shfl_sync(FULL, fA.z, 3, 4);
        float cIx = __shfl_sync(FULL, fI.w, 0, 4);
        float cIy = __shfl_sync(FULL, fI.w, 1, 4);
        float cIz = __shfl_sync(FULL, fI.w, 2, 4);
        float nIx = __shfl_sync(FULL, fI.x, 3, 4);
        float nIy = __shfl_sync(FULL, fI.y, 3, 4);
        float nIz = __shfl_sync(FULL, fI.z, 3, 4);

        if (valid && lc < 3) {
            // direction 1: my I vertex inside A's cone field
            float dx = fI.x - cAx, dy = fI.y - cAy, dz = fI.z - cAz;
            float r2 = fmaf(dx, dx, fmaf(dy, dy, dz * dz));
            if (r2 < SIGMA2_F) {
                float h = fmaf(dx, nAx, fmaf(dy, nAy, dz * nAz));
                if (h < 0.0f) pen = fmaf((SIGMA_F - sqrtf(r2)) * h, h, pen);
            }
            // direction 2: my A vertex inside I's cone field
            float ex = fA.x - cIx, ey = fA.y - cIy, ez = fA.z - cIz;
            float s2 = fmaf(ex, ex, fmaf(ey, ey, ez * ez));
            if (s2 < SIGMA2_F) {
                float g = fmaf(ex, nIx, fmaf(ey, nIy, ez * nIz));
                if (g < 0.0f) pen = fmaf((SIGMA_F - sqrtf(s2)) * g, g, pen);
            }
        }
    }

    // warp reduce: every lane's contribution summed exactly once
    #pragma unroll
    for (int o = 16; o > 0; o >>= 1)
        pen += __shfl_down_sync(FULL, pen, o);
    if (lane == 0) s_wsum[w] = pen;
    __syncthreads();
    if (w == 0) {
        float v = (lane < TPB / 32) ? s_wsum[lane] : 0.0f;
        #pragma unroll
        for (int o = 4; o > 0; o >>= 1)
            v += __shfl_down_sync(0xffu, v, o);
        if (lane == 0) {
            atomicAdd(&g_acc, (double)v);
            __threadfence();
            unsigned int done = atomicAdd(&g_cnt, 1u);
            if (done == (unsigned int)(GRID_PAIR - 1)) {
                double total = atomicAdd(&g_acc, 0.0);
                out[0] = (float)(total * (1.0 / (double)BB)) * weight[0];
            }
        }
    }
}

extern "C" void kernel_launch(void* const* d_in, const int* in_sizes, int n_in,
                              void* d_out, int out_size)
{
    // metadata order: pose, joints, points, keypoints, vertices, weight, faces, collision_idxs
    const float* vertices = (const float*)d_in[4];
    const float* weight   = (const float*)d_in[5];
    const int*   faces    = (const int*)d_in[6];
    const int2*  cidx     = (const int2*)d_in[7];

    build_recs_kernel<<<(NREC + 255) / 256, 256>>>(vertices, faces);
    pair_kernel<<<GRID_PAIR, TPB>>>(cidx, weight, (float*)d_out);
}